// round 5
// baseline (speedup 1.0000x reference)
#include <cuda_runtime.h>
#include <cuda_bf16.h>
#include <cstdint>

#define NODES_TOTAL 100000
#define NNODES      20000
#define TN          50
#define INF         256
#define HIDF        256
#define OUTF        256
#define CATF        512

// Scratch (static __device__ arrays: allocation-free per harness rules)
__device__ __align__(16) __nv_bfloat16 g_qh[(size_t)NODES_TOTAL * HIDF]; // 51.2 MB (L2-resident)
__device__ __align__(16) float         g_cat[(size_t)NNODES * CATF];     // 41 MB

// ---------------------------------------------------------------------------
// helpers
// ---------------------------------------------------------------------------
__device__ __forceinline__ uint32_t f2tf32(float x) {
    uint32_t r;
    asm("cvt.rna.tf32.f32 %0, %1;" : "=r"(r) : "f"(x));
    return r;
}

__device__ __forceinline__ void mma_tf32(float c[4],
                                         uint32_t a0, uint32_t a1, uint32_t a2, uint32_t a3,
                                         uint32_t b0, uint32_t b1) {
    asm volatile("mma.sync.aligned.m16n8k8.row.col.f32.tf32.tf32.f32 "
                 "{%0,%1,%2,%3}, {%4,%5,%6,%7}, {%8,%9}, {%0,%1,%2,%3};"
                 : "+f"(c[0]), "+f"(c[1]), "+f"(c[2]), "+f"(c[3])
                 : "r"(a0), "r"(a1), "r"(a2), "r"(a3), "r"(b0), "r"(b1));
}

// ---------------------------------------------------------------------------
// TF32 HMMA GEMM:  C[m, n0..n0+127] = relu( sum_k A[m,k]*B[n,k] + bias[n] )
// A: [M, K] row-major fp32, B: [256, K] row-major fp32 (torch weight layout).
// CTA tile 128x128, 4 warps (each 64x64), K-tile 16.
// tf32 rounding applied ONCE at the global->smem store (LDG -> cvt.rna -> STS);
// the mma inner loop reads raw tf32 bit patterns from smem (no cvt).
// Single smem buffer; register prefetch of tile k+1 overlaps compute of tile k.
// Grid x: (2 colTiles fastest, then rowTiles) so A rows are L2-hot on the
// second N-tile.
// ---------------------------------------------------------------------------
#define KT   16
#define SROW 20   // padded smem row stride (floats): conflict-free reads, 16B-aligned stores

template <int NT, bool BF16OUT>
__global__ __launch_bounds__(128) void gemm_hmma_kernel(
    const float* __restrict__ A, const float* __restrict__ B,
    const float* __restrict__ bias, void* __restrict__ Cv, int M)
{
    __shared__ float sA[128 * SROW];
    __shared__ float sB[128 * SROW];

    const int tid  = threadIdx.x;
    const int warp = tid >> 5;
    const int lane = tid & 31;
    const int g    = lane >> 2;   // groupID 0..7
    const int tg   = lane & 3;    // threadID in group 0..3
    const int m0   = (int)(blockIdx.x >> 1) * 128;
    const int n0   = (int)(blockIdx.x & 1) * 128;
    const int wm   = (warp >> 1) * 64;   // warp M offset
    const int wn   = (warp & 1) * 64;    // warp N offset
    const int K    = NT * KT;

    const int r0 = tid >> 2;          // 0..31  (base row for staging loads)
    const int c4 = (tid & 3) * 4;     // 0,4,8,12 (col within K-tile)

    float acc[4][8][4];
    #pragma unroll
    for (int i = 0; i < 4; i++)
        #pragma unroll
        for (int j = 0; j < 8; j++)
            #pragma unroll
            for (int r = 0; r < 4; r++) acc[i][j][r] = 0.f;

    // ---- prologue: stage tile 0 (cvt to tf32 at store) ----
    #pragma unroll
    for (int i = 0; i < 4; i++) {
        const int row = r0 + 32 * i;
        float4 va = make_float4(0.f, 0.f, 0.f, 0.f);
        if (m0 + row < M) va = *(const float4*)(A + (size_t)(m0 + row) * K + c4);
        const float4 vb = *(const float4*)(B + (size_t)(n0 + row) * K + c4);
        *(uint4*)&sA[row * SROW + c4] =
            make_uint4(f2tf32(va.x), f2tf32(va.y), f2tf32(va.z), f2tf32(va.w));
        *(uint4*)&sB[row * SROW + c4] =
            make_uint4(f2tf32(vb.x), f2tf32(vb.y), f2tf32(vb.z), f2tf32(vb.w));
    }
    __syncthreads();

    #pragma unroll 1
    for (int kt = 0; kt < NT; kt++) {
        // ---- prefetch tile kt+1 into registers (overlaps mma below) ----
        float4 pa[4], pb[4];
        if (kt + 1 < NT) {
            const int kk = (kt + 1) * KT;
            #pragma unroll
            for (int i = 0; i < 4; i++) {
                const int row = r0 + 32 * i;
                pa[i] = (m0 + row < M)
                      ? *(const float4*)(A + (size_t)(m0 + row) * K + kk + c4)
                      : make_float4(0.f, 0.f, 0.f, 0.f);
                pb[i] = *(const float4*)(B + (size_t)(n0 + row) * K + kk + c4);
            }
        }

        // ---- compute on tile kt (raw tf32 bits from smem; no cvt) ----
        #pragma unroll
        for (int ks = 0; ks < 2; ks++) {
            const int k = ks * 8 + tg;
            uint32_t af[4][4];
            #pragma unroll
            for (int mf = 0; mf < 4; mf++) {
                const int rb_ = wm + mf * 16;
                af[mf][0] = __float_as_uint(sA[(rb_ + g)     * SROW + k]);
                af[mf][1] = __float_as_uint(sA[(rb_ + g + 8) * SROW + k]);
                af[mf][2] = __float_as_uint(sA[(rb_ + g)     * SROW + k + 4]);
                af[mf][3] = __float_as_uint(sA[(rb_ + g + 8) * SROW + k + 4]);
            }
            #pragma unroll
            for (int nf = 0; nf < 8; nf++) {
                const int nb_ = wn + nf * 8;
                const uint32_t b0 = __float_as_uint(sB[(nb_ + g) * SROW + k]);
                const uint32_t b1 = __float_as_uint(sB[(nb_ + g) * SROW + k + 4]);
                #pragma unroll
                for (int mf = 0; mf < 4; mf++)
                    mma_tf32(acc[mf][nf], af[mf][0], af[mf][1], af[mf][2], af[mf][3],
                             b0, b1);
            }
        }
        __syncthreads();

        // ---- stage tile kt+1 (cvt once at store) ----
        if (kt + 1 < NT) {
            #pragma unroll
            for (int i = 0; i < 4; i++) {
                const int row = r0 + 32 * i;
                *(uint4*)&sA[row * SROW + c4] =
                    make_uint4(f2tf32(pa[i].x), f2tf32(pa[i].y), f2tf32(pa[i].z), f2tf32(pa[i].w));
                *(uint4*)&sB[row * SROW + c4] =
                    make_uint4(f2tf32(pb[i].x), f2tf32(pb[i].y), f2tf32(pb[i].z), f2tf32(pb[i].w));
            }
            __syncthreads();
        }
    }

    // ---- epilogue: bias + relu, store (C row stride fixed at 256 elements) ----
    #pragma unroll
    for (int mf = 0; mf < 4; mf++) {
        #pragma unroll
        for (int half = 0; half < 2; half++) {
            const int m = m0 + wm + mf * 16 + g + half * 8;
            if (m < M) {
                #pragma unroll
                for (int nf = 0; nf < 8; nf++) {
                    const int c = n0 + wn + nf * 8 + tg * 2;
                    const float v0 = fmaxf(acc[mf][nf][half * 2 + 0] + __ldg(&bias[c]),     0.f);
                    const float v1 = fmaxf(acc[mf][nf][half * 2 + 1] + __ldg(&bias[c + 1]), 0.f);
                    if (BF16OUT) {
                        __nv_bfloat162 p = __float22bfloat162_rn(make_float2(v0, v1));
                        *(__nv_bfloat162*)((__nv_bfloat16*)Cv + (size_t)m * 256 + c) = p;
                    } else {
                        *(float2*)((float*)Cv + (size_t)m * 256 + c) = make_float2(v0, v1);
                    }
                }
            }
        }
    }
}

// ---------------------------------------------------------------------------
// Aggregation: h_agg[n] = sum_t w[n,t]*QH[nb[n,t]] / sum_t w[n,t]
// QH is bf16 [100000, 256] (L2-resident). One warp per node; also copies
// h[nodeset[n]] into the first half of the concat row.
// ---------------------------------------------------------------------------
__global__ __launch_bounds__(256) void agg_kernel(
    const float* __restrict__ h, const int* __restrict__ nodeset,
    const int* __restrict__ nb_nodes, const float* __restrict__ nb_w)
{
    __shared__ int   s_idx[8][TN];
    __shared__ float s_w[8][TN];

    const int tid  = threadIdx.x;
    const int warp = tid >> 5;
    const int lane = tid & 31;
    const int n    = blockIdx.x * 8 + warp;   // 20000/8 = 2500 blocks exact

    for (int j = lane; j < TN; j += 32) {
        s_idx[warp][j] = nb_nodes[n * TN + j];
        s_w[warp][j]   = nb_w[n * TN + j];
    }
    __syncwarp();

    float wsum = 0.f;
    #pragma unroll
    for (int t = 0; t < TN; t++) wsum += s_w[warp][t];   // smem broadcast

    const int colb = lane * 8;   // bf16 column base for this lane
    float acc[8];
    #pragma unroll
    for (int i = 0; i < 8; i++) acc[i] = 0.f;

    #pragma unroll 5
    for (int t = 0; t < TN; t++) {
        const int   idx = s_idx[warp][t];
        const float w   = s_w[warp][t];
        const uint4 q   = *(const uint4*)(g_qh + (size_t)idx * HIDF + colb);
        const uint32_t u[4] = {q.x, q.y, q.z, q.w};
        #pragma unroll
        for (int i = 0; i < 4; i++) {
            const float lo = __uint_as_float(u[i] << 16);
            const float hi = __uint_as_float(u[i] & 0xffff0000u);
            acc[2 * i]     += w * lo;
            acc[2 * i + 1] += w * hi;
        }
    }
    const float inv = 1.f / wsum;
    float4 o0 = make_float4(acc[0] * inv, acc[1] * inv, acc[2] * inv, acc[3] * inv);
    float4 o1 = make_float4(acc[4] * inv, acc[5] * inv, acc[6] * inv, acc[7] * inv);
    float* dst = g_cat + (size_t)n * CATF + INF + colb;
    *(float4*)(dst)     = o0;
    *(float4*)(dst + 4) = o1;

    // self-feature copy into the first half of the concat row (8 floats/lane)
    const int self = nodeset[n];
    const float4* src = (const float4*)(h + (size_t)self * INF);
    float4* sdst = (float4*)(g_cat + (size_t)n * CATF);
    sdst[lane * 2]     = src[lane * 2];
    sdst[lane * 2 + 1] = src[lane * 2 + 1];
}

// ---------------------------------------------------------------------------
// In-place row L2 normalize of d_out [20000, 256]; one warp per row
// ---------------------------------------------------------------------------
__global__ __launch_bounds__(256) void norm_kernel(float* __restrict__ out)
{
    const int gwarp = (blockIdx.x * blockDim.x + threadIdx.x) >> 5;
    const int lane  = threadIdx.x & 31;
    if (gwarp >= NNODES) return;
    float* row = out + (size_t)gwarp * OUTF;

    float4 v0 = *(float4*)&row[lane * 4];
    float4 v1 = *(float4*)&row[128 + lane * 4];
    float ss = v0.x * v0.x + v0.y * v0.y + v0.z * v0.z + v0.w * v0.w
             + v1.x * v1.x + v1.y * v1.y + v1.z * v1.z + v1.w * v1.w;
    #pragma unroll
    for (int o = 16; o; o >>= 1) ss += __shfl_xor_sync(0xffffffffu, ss, o);
    const float inv = rsqrtf(ss);
    v0.x *= inv; v0.y *= inv; v0.z *= inv; v0.w *= inv;
    v1.x *= inv; v1.y *= inv; v1.z *= inv; v1.w *= inv;
    *(float4*)&row[lane * 4]       = v0;
    *(float4*)&row[128 + lane * 4] = v1;
}

// ---------------------------------------------------------------------------
extern "C" void kernel_launch(void* const* d_in, const int* in_sizes, int n_in,
                              void* d_out, int out_size)
{
    const float* h        = (const float*)d_in[0];
    const int*   nodeset  = (const int*)d_in[1];
    const int*   nb_nodes = (const int*)d_in[2];
    const float* nb_w     = (const float*)d_in[3];
    const float* Qw       = (const float*)d_in[4];
    const float* Qb       = (const float*)d_in[5];
    const float* Ww       = (const float*)d_in[6];
    const float* Wb       = (const float*)d_in[7];
    float*       out      = (float*)d_out;

    __nv_bfloat16* qh = nullptr;
    float*         cat = nullptr;
    cudaGetSymbolAddress((void**)&qh,  g_qh);
    cudaGetSymbolAddress((void**)&cat, g_cat);

    // 1) QH = relu(h @ Qw^T + Qb) -> bf16 [100000, 256], K=256 (NT=16)
    {
        const int tilesM = (NODES_TOTAL + 127) / 128;   // 782
        gemm_hmma_kernel<16, true><<<tilesM * 2, 128>>>(h, Qw, Qb, qh, NODES_TOTAL);
    }
    // 2) aggregate + self gather -> g_cat [20000, 512]
    agg_kernel<<<NNODES / 8, 256>>>(h, nodeset, nb_nodes, nb_w);

    // 3) out = relu(g_cat @ Ww^T + Wb)  [20000, 256], K=512 (NT=32)
    {
        const int tilesM = (NNODES + 127) / 128;        // 157
        gemm_hmma_kernel<32, false><<<tilesM * 2, 128>>>(cat, Ww, Wb, out, NNODES);
    }
    // 4) in-place L2 normalize
    norm_kernel<<<(NNODES * 32 + 255) / 256, 256>>>(out);
}

// round 6
// speedup vs baseline: 1.1649x; 1.1649x over previous
#include <cuda_runtime.h>
#include <cuda_fp16.h>
#include <cstdint>

#define NODES_TOTAL 100000
#define NNODES      20000
#define TN          50
#define INF         256
#define HIDF        256
#define OUTF        256
#define CATF        512

// Scratch (static __device__ arrays: allocation-free per harness rules)
__device__ __align__(16) __half g_qh[(size_t)NODES_TOTAL * HIDF];  // 51.2 MB (L2-resident)
__device__ __align__(16) __half g_cat[(size_t)NNODES * CATF];      // 20.5 MB

// ---------------------------------------------------------------------------
// helpers
// ---------------------------------------------------------------------------
__device__ __forceinline__ void mma_f16(float c[4], const uint32_t a[4],
                                        uint32_t b0, uint32_t b1) {
    asm volatile("mma.sync.aligned.m16n8k16.row.col.f32.f16.f16.f32 "
                 "{%0,%1,%2,%3}, {%4,%5,%6,%7}, {%8,%9}, {%0,%1,%2,%3};"
                 : "+f"(c[0]), "+f"(c[1]), "+f"(c[2]), "+f"(c[3])
                 : "r"(a[0]), "r"(a[1]), "r"(a[2]), "r"(a[3]), "r"(b0), "r"(b1));
}

__device__ __forceinline__ void ldmatrix_x4(uint32_t r[4], uint32_t saddr) {
    asm volatile("ldmatrix.sync.aligned.m8n8.x4.shared.b16 {%0,%1,%2,%3}, [%4];"
                 : "=r"(r[0]), "=r"(r[1]), "=r"(r[2]), "=r"(r[3]) : "r"(saddr));
}

__device__ __forceinline__ uint32_t pack_h2(float x, float y) {
    __half2 h = __float22half2_rn(make_float2(x, y));
    return *(uint32_t*)&h;
}

// ---------------------------------------------------------------------------
// fp16 HMMA GEMM:  C[m, n0..n0+127] = relu( sum_k A[m,k]*B[n,k] + bias[n] )
// A: [M, K] row-major (fp32 or fp16 per A_FP16), B: [256, K] row-major fp32.
// CTA tile 128x128, 8 warps (each 64x32), K chunked by 32 elements.
// f32 -> f16 conversion once at the global->smem staging store.
// Fragments loaded via ldmatrix (smem row stride 40 halves = 80B: 8 rows at
// 80B stride mod 128 cover all eight 16B groups -> conflict-free ldmatrix).
// Double smem buffer; register prefetch of chunk c+1 overlaps compute of c.
// Grid.x = tileM*2 + colTile (colTile fastest -> A rows L2-hot on 2nd tile).
// ---------------------------------------------------------------------------
#define SROWH 40   // smem row stride in halves

template <int NCHUNK, bool A_FP16, bool OUT_FP16>
__global__ __launch_bounds__(256) void gemm_f16_kernel(
    const void* __restrict__ Av, const float* __restrict__ B,
    const float* __restrict__ bias, void* __restrict__ Cv, int M)
{
    __shared__ __half sA[2][128 * SROWH];
    __shared__ __half sB[2][128 * SROWH];

    const int tid  = threadIdx.x;
    const int warp = tid >> 5;
    const int lane = tid & 31;
    const int g    = lane >> 2;
    const int tg   = lane & 3;
    const int m0   = (int)(blockIdx.x >> 1) * 128;
    const int n0   = (int)(blockIdx.x & 1) * 128;
    const int wm   = (warp >> 2) * 64;   // warp M offset
    const int wn   = (warp & 3) * 32;    // warp N offset
    const int K    = NCHUNK * 32;

    // staging slots: each thread owns row (tid>>1), half-row part (tid&1)*16
    const int srow = tid >> 1;
    const int part = (tid & 1) * 16;

    float acc[4][4][4];
    #pragma unroll
    for (int i = 0; i < 4; i++)
        #pragma unroll
        for (int j = 0; j < 4; j++)
            #pragma unroll
            for (int r = 0; r < 4; r++) acc[i][j][r] = 0.f;

    const float*  A32 = (const float*)Av;
    const __half* A16 = (const __half*)Av;

    // ---- stage chunk 0 into buffer 0 ----
    {
        const bool va = (m0 + srow) < M;
        #pragma unroll
        for (int i = 0; i < 4; i++) {
            const int kc = part + i * 4;
            uint2 apk;
            if (A_FP16) {
                apk = va ? *(const uint2*)(A16 + (size_t)(m0 + srow) * K + kc)
                         : make_uint2(0u, 0u);
            } else {
                float4 v = va ? *(const float4*)(A32 + (size_t)(m0 + srow) * K + kc)
                              : make_float4(0.f, 0.f, 0.f, 0.f);
                apk = make_uint2(pack_h2(v.x, v.y), pack_h2(v.z, v.w));
            }
            *(uint2*)&sA[0][srow * SROWH + kc] = apk;
            float4 vb = *(const float4*)(B + (size_t)(n0 + srow) * K + kc);
            *(uint2*)&sB[0][srow * SROWH + kc] =
                make_uint2(pack_h2(vb.x, vb.y), pack_h2(vb.z, vb.w));
        }
    }
    __syncthreads();

    const uint32_t uA0 = (uint32_t)__cvta_generic_to_shared(&sA[0][0]);
    const uint32_t uA1 = (uint32_t)__cvta_generic_to_shared(&sA[1][0]);
    const uint32_t uB0 = (uint32_t)__cvta_generic_to_shared(&sB[0][0]);
    const uint32_t uB1 = (uint32_t)__cvta_generic_to_shared(&sB[1][0]);

    // fragment ldmatrix byte offsets (within a buffer)
    const uint32_t offA = (uint32_t)(((lane & 15) * SROWH + (lane >> 4) * 8) * 2);
    const uint32_t offB = (uint32_t)((((lane >> 4) * 8 + (lane & 7)) * SROWH
                                      + ((lane >> 3) & 1) * 8) * 2);

    #pragma unroll 1
    for (int c = 0; c < NCHUNK; c++) {
        const uint32_t ubA = (c & 1) ? uA1 : uA0;
        const uint32_t ubB = (c & 1) ? uB1 : uB0;

        // ---- prefetch chunk c+1 into registers (overlaps compute) ----
        uint2  pa16[4];
        float4 pa32[4], pb[4];
        const bool havenext = (c + 1 < NCHUNK);
        if (havenext) {
            const int kk = (c + 1) * 32 + part;
            const bool va = (m0 + srow) < M;
            #pragma unroll
            for (int i = 0; i < 4; i++) {
                if (A_FP16) {
                    pa16[i] = va ? *(const uint2*)(A16 + (size_t)(m0 + srow) * K + kk + i * 4)
                                 : make_uint2(0u, 0u);
                } else {
                    pa32[i] = va ? *(const float4*)(A32 + (size_t)(m0 + srow) * K + kk + i * 4)
                                 : make_float4(0.f, 0.f, 0.f, 0.f);
                }
                pb[i] = *(const float4*)(B + (size_t)(n0 + srow) * K + kk + i * 4);
            }
        }

        // ---- compute chunk c ----
        #pragma unroll
        for (int ks = 0; ks < 2; ks++) {
            uint32_t af[4][4];
            #pragma unroll
            for (int mf = 0; mf < 4; mf++)
                ldmatrix_x4(af[mf], ubA + offA
                            + (uint32_t)(((wm + mf * 16) * SROWH + ks * 16) * 2));
            uint32_t bf[2][4];
            #pragma unroll
            for (int p = 0; p < 2; p++)
                ldmatrix_x4(bf[p], ubB + offB
                            + (uint32_t)(((wn + p * 16) * SROWH + ks * 16) * 2));
            #pragma unroll
            for (int mf = 0; mf < 4; mf++)
                #pragma unroll
                for (int nf = 0; nf < 4; nf++)
                    mma_f16(acc[mf][nf], af[mf], bf[nf >> 1][(nf & 1) * 2],
                            bf[nf >> 1][(nf & 1) * 2 + 1]);
        }
        __syncthreads();

        // ---- store prefetched chunk c+1 into other buffer ----
        if (havenext) {
            const uint32_t nb = (c + 1) & 1;
            __half* dA = nb ? &sA[1][0] : &sA[0][0];
            __half* dB = nb ? &sB[1][0] : &sB[0][0];
            #pragma unroll
            for (int i = 0; i < 4; i++) {
                const int kc = part + i * 4;
                uint2 apk;
                if (A_FP16) apk = pa16[i];
                else apk = make_uint2(pack_h2(pa32[i].x, pa32[i].y),
                                      pack_h2(pa32[i].z, pa32[i].w));
                *(uint2*)&dA[srow * SROWH + kc] = apk;
                *(uint2*)&dB[srow * SROWH + kc] =
                    make_uint2(pack_h2(pb[i].x, pb[i].y), pack_h2(pb[i].z, pb[i].w));
            }
            __syncthreads();
        }
    }

    // ---- epilogue: bias + relu, store (C row stride 256 elements) ----
    #pragma unroll
    for (int mf = 0; mf < 4; mf++) {
        #pragma unroll
        for (int half = 0; half < 2; half++) {
            const int m = m0 + wm + mf * 16 + g + half * 8;
            if (m < M) {
                #pragma unroll
                for (int nf = 0; nf < 4; nf++) {
                    const int cc = n0 + wn + nf * 8 + tg * 2;
                    const float v0 = fmaxf(acc[mf][nf][half * 2 + 0] + __ldg(&bias[cc]),     0.f);
                    const float v1 = fmaxf(acc[mf][nf][half * 2 + 1] + __ldg(&bias[cc + 1]), 0.f);
                    if (OUT_FP16) {
                        uint32_t p = pack_h2(v0, v1);
                        *(uint32_t*)((__half*)Cv + (size_t)m * 256 + cc) = p;
                    } else {
                        *(float2*)((float*)Cv + (size_t)m * 256 + cc) = make_float2(v0, v1);
                    }
                }
            }
        }
    }
}

// ---------------------------------------------------------------------------
// Aggregation: h_agg[n] = sum_t w[n,t]*QH[nb[n,t]] / sum_t w[n,t]
// QH is fp16 [100000, 256] (L2-resident). One warp per node; also copies
// h[nodeset[n]] (fp32 -> fp16) into the first half of the fp16 concat row.
// ---------------------------------------------------------------------------
__global__ __launch_bounds__(256) void agg_kernel(
    const float* __restrict__ h, const int* __restrict__ nodeset,
    const int* __restrict__ nb_nodes, const float* __restrict__ nb_w)
{
    __shared__ int   s_idx[8][TN];
    __shared__ float s_w[8][TN];

    const int tid  = threadIdx.x;
    const int warp = tid >> 5;
    const int lane = tid & 31;
    const int n    = blockIdx.x * 8 + warp;   // 20000/8 = 2500 blocks exact

    for (int j = lane; j < TN; j += 32) {
        s_idx[warp][j] = nb_nodes[n * TN + j];
        s_w[warp][j]   = nb_w[n * TN + j];
    }
    __syncwarp();

    float wsum = 0.f;
    #pragma unroll
    for (int t = 0; t < TN; t++) wsum += s_w[warp][t];   // smem broadcast

    const int colb = lane * 8;   // half column base for this lane
    float acc[8];
    #pragma unroll
    for (int i = 0; i < 8; i++) acc[i] = 0.f;

    #pragma unroll 5
    for (int t = 0; t < TN; t++) {
        const int   idx = s_idx[warp][t];
        const float w   = s_w[warp][t];
        union { uint4 u; __half2 h2[4]; } q;
        q.u = *(const uint4*)(g_qh + (size_t)idx * HIDF + colb);
        #pragma unroll
        for (int i = 0; i < 4; i++) {
            const float2 f = __half22float2(q.h2[i]);
            acc[2 * i]     += w * f.x;
            acc[2 * i + 1] += w * f.y;
        }
    }
    const float inv = 1.f / wsum;
    union { uint4 u; __half2 h2[4]; } o;
    #pragma unroll
    for (int i = 0; i < 4; i++)
        o.h2[i] = __float22half2_rn(make_float2(acc[2 * i] * inv, acc[2 * i + 1] * inv));
    *(uint4*)(g_cat + (size_t)n * CATF + INF + colb) = o.u;

    // self-feature copy (fp32 -> fp16) into first half of concat row
    const int self = nodeset[n];
    const float4 s0 = *(const float4*)(h + (size_t)self * INF + colb);
    const float4 s1 = *(const float4*)(h + (size_t)self * INF + colb + 4);
    union { uint4 u; __half2 h2[4]; } sc;
    sc.h2[0] = __float22half2_rn(make_float2(s0.x, s0.y));
    sc.h2[1] = __float22half2_rn(make_float2(s0.z, s0.w));
    sc.h2[2] = __float22half2_rn(make_float2(s1.x, s1.y));
    sc.h2[3] = __float22half2_rn(make_float2(s1.z, s1.w));
    *(uint4*)(g_cat + (size_t)n * CATF + colb) = sc.u;
}

// ---------------------------------------------------------------------------
// In-place row L2 normalize of d_out [20000, 256]; one warp per row
// ---------------------------------------------------------------------------
__global__ __launch_bounds__(256) void norm_kernel(float* __restrict__ out)
{
    const int gwarp = (blockIdx.x * blockDim.x + threadIdx.x) >> 5;
    const int lane  = threadIdx.x & 31;
    if (gwarp >= NNODES) return;
    float* row = out + (size_t)gwarp * OUTF;

    float4 v0 = *(float4*)&row[lane * 4];
    float4 v1 = *(float4*)&row[128 + lane * 4];
    float ss = v0.x * v0.x + v0.y * v0.y + v0.z * v0.z + v0.w * v0.w
             + v1.x * v1.x + v1.y * v1.y + v1.z * v1.z + v1.w * v1.w;
    #pragma unroll
    for (int o = 16; o; o >>= 1) ss += __shfl_xor_sync(0xffffffffu, ss, o);
    const float inv = rsqrtf(ss);
    v0.x *= inv; v0.y *= inv; v0.z *= inv; v0.w *= inv;
    v1.x *= inv; v1.y *= inv; v1.z *= inv; v1.w *= inv;
    *(float4*)&row[lane * 4]       = v0;
    *(float4*)&row[128 + lane * 4] = v1;
}

// ---------------------------------------------------------------------------
extern "C" void kernel_launch(void* const* d_in, const int* in_sizes, int n_in,
                              void* d_out, int out_size)
{
    const float* h        = (const float*)d_in[0];
    const int*   nodeset  = (const int*)d_in[1];
    const int*   nb_nodes = (const int*)d_in[2];
    const float* nb_w     = (const float*)d_in[3];
    const float* Qw       = (const float*)d_in[4];
    const float* Qb       = (const float*)d_in[5];
    const float* Ww       = (const float*)d_in[6];
    const float* Wb       = (const float*)d_in[7];
    float*       out      = (float*)d_out;

    __half* qh  = nullptr;
    __half* cat = nullptr;
    cudaGetSymbolAddress((void**)&qh,  g_qh);
    cudaGetSymbolAddress((void**)&cat, g_cat);

    // 1) QH = relu(h @ Qw^T + Qb) -> fp16 [100000, 256], K=256 (8 chunks)
    {
        const int tilesM = (NODES_TOTAL + 127) / 128;   // 782
        gemm_f16_kernel<8, false, true><<<tilesM * 2, 256>>>(h, Qw, Qb, qh, NODES_TOTAL);
    }
    // 2) aggregate + self gather -> g_cat fp16 [20000, 512]
    agg_kernel<<<NNODES / 8, 256>>>(h, nodeset, nb_nodes, nb_w);

    // 3) out = relu(g_cat @ Ww^T + Wb)  [20000, 256], K=512 (16 chunks)
    {
        const int tilesM = (NNODES + 127) / 128;        // 157
        gemm_f16_kernel<16, true, false><<<tilesM * 2, 256>>>(cat, Ww, Wb, out, NNODES);
    }
    // 4) in-place L2 normalize
    norm_kernel<<<(NNODES * 32 + 255) / 256, 256>>>(out);
}